// round 2
// baseline (speedup 1.0000x reference)
#include <cuda_runtime.h>
#include <mma.h>
#include <type_traits>

using namespace nvcuda;

#define Bb 2
#define Ss 2048
#define Nn 4096
#define Dd 1024
#define Vv 32000
#define NLAYERS 6
#define LN_EPS 1e-5f
#define BSROWS (Bb * Ss) /* 4096 */

// ---------------- scratch (static device globals; no allocation) ----------
__device__ float g_v[BSROWS * Dd];   // v_ast  [B*S, D]
__device__ float g_x[BSROWS * Nn];   // x      [B*S, N]
__device__ float g_kv[Bb * Nn * Dd]; // kv     [B, N, D]
__device__ float g_a[BSROWS * Dd];   // a_ast  [B*S, D]
__device__ float g_y[BSROWS * Nn];   // y      [B*S, N]
__device__ float g_t[BSROWS * Dd];   // y @ E  [B*S, D]

// ---------------- embedding gather ---------------------------------------
__global__ void gather_kernel(const int* __restrict__ idx,
                              const float* __restrict__ emb,
                              float* __restrict__ out) {
    int row = blockIdx.x;            // 0..B*S-1
    int t = threadIdx.x;             // 0..255 (D/4 = 256 float4)
    const float4* src = (const float4*)(emb + (size_t)idx[row] * Dd);
    float4* dst = (float4*)(out + (size_t)row * Dd);
    dst[t] = src[t];
}

// ---------------- fused v = LN(v + LN(t)) ---------------------------------
__device__ __forceinline__ void block_reduce2(float& s, float& s2, float* sh) {
#pragma unroll
    for (int o = 16; o > 0; o >>= 1) {
        s += __shfl_down_sync(0xFFFFFFFFu, s, o);
        s2 += __shfl_down_sync(0xFFFFFFFFu, s2, o);
    }
    int warp = threadIdx.x >> 5, lane = threadIdx.x & 31;
    if (lane == 0) { sh[warp * 2] = s; sh[warp * 2 + 1] = s2; }
    __syncthreads();
    float ts = 0.f, ts2 = 0.f;
#pragma unroll
    for (int w = 0; w < 8; w++) { ts += sh[w * 2]; ts2 += sh[w * 2 + 1]; }
    s = ts; s2 = ts2;
    __syncthreads();
}

__global__ void ln_res_ln_kernel(float* __restrict__ v, const float* __restrict__ t) {
    __shared__ float sh[16];
    int row = blockIdx.x;
    int tid = threadIdx.x;  // 256 threads, 4 elems each (D=1024)
    const float4 tv = ((const float4*)(t + (size_t)row * Dd))[tid];
    float4 vv = ((float4*)(v + (size_t)row * Dd))[tid];

    float s = tv.x + tv.y + tv.z + tv.w;
    float s2 = tv.x * tv.x + tv.y * tv.y + tv.z * tv.z + tv.w * tv.w;
    block_reduce2(s, s2, sh);
    float m = s * (1.0f / Dd);
    float inv = rsqrtf(s2 * (1.0f / Dd) - m * m + LN_EPS);

    float4 u;
    u.x = vv.x + (tv.x - m) * inv;
    u.y = vv.y + (tv.y - m) * inv;
    u.z = vv.z + (tv.z - m) * inv;
    u.w = vv.w + (tv.w - m) * inv;

    s = u.x + u.y + u.z + u.w;
    s2 = u.x * u.x + u.y * u.y + u.z * u.z + u.w * u.w;
    block_reduce2(s, s2, sh);
    m = s * (1.0f / Dd);
    inv = rsqrtf(s2 * (1.0f / Dd) - m * m + LN_EPS);

    vv.x = (u.x - m) * inv;
    vv.y = (u.y - m) * inv;
    vv.z = (u.z - m) * inv;
    vv.w = (u.w - m) * inv;
    ((float4*)(v + (size_t)row * Dd))[tid] = vv;
}

// ---------------- 3xTF32 tensor-core GEMM (fp32-accurate) -----------------
// C[M,Ncol] = op(A) @ B (+ epilogue).  TRANSA=0: A[M,K] row-major.
// TRANSA=1: A stored [K,M] row-major (op(A)=A^T).  B[K,Ncol] row-major.
// Batched via blockIdx.z with element strides sA/sB/sC (0 for shared weights).
// EPI: 0 = none, 1 = relu, 2 = relu * Aux[m,n] (Aux same shape/stride as C).
constexpr int BM = 128, BN = 64, BK = 32;
enum { EPI_NONE = 0, EPI_RELU = 1, EPI_RELU_MUL = 2 };

template <bool TRANSA, int EPI>
__global__ void __launch_bounds__(256, 2)
gemm_tf32(const float* __restrict__ A, const float* __restrict__ B,
          float* __restrict__ C, const float* __restrict__ Aux,
          int M, int Ncol, int K, long sA, long sB, long sC) {
    // shared tiles (padded; strides keep float4 stores 16B-aligned)
    __shared__ __align__(16) float As[TRANSA ? (BK * (BM + 4)) : (BM * (BK + 4))];
    __shared__ __align__(16) float Bs[BK * (BN + 4)];
    __shared__ __align__(16) float EpiS[(EPI == EPI_RELU_MUL) ? (8 * 16 * 20) : 8];

    const int bz = blockIdx.z;
    A += (long)bz * sA;
    B += (long)bz * sB;
    C += (long)bz * sC;

    const int rowBase = blockIdx.y * BM;
    const int colBase = blockIdx.x * BN;
    const int tid = threadIdx.x;
    const int warpId = tid >> 5;
    const int lane = tid & 31;
    const int wr = warpId >> 1;  // 0..3 (row of warp grid)
    const int wc = warpId & 1;   // 0..1 (col of warp grid)

    const int lda = TRANSA ? M : K;
    const int ldb = Ncol;
    const int ldc = Ncol;

    // global-load index split
    const int ar = tid >> 3;          // TRANSA=0: row 0..31 (+i*32)
    const int ac = (tid & 7) * 4;     // TRANSA=0: k col
    const int ak = tid >> 5;          // TRANSA=1: k row 0..7 (+i*8)
    const int am = (tid & 31) * 4;    // TRANSA=1: m col
    const int bk = tid >> 4;          // B: k row 0..15 (+i*16)
    const int bc = (tid & 15) * 4;    // B: n col

    float4 pa[4], pb[2];
    const int KT = K / BK;

    auto loadA = [&](int kBase) {
        if constexpr (!TRANSA) {
#pragma unroll
            for (int i = 0; i < 4; i++)
                pa[i] = *(const float4*)(A + (long)(rowBase + ar + i * 32) * lda + kBase + ac);
        } else {
#pragma unroll
            for (int i = 0; i < 4; i++)
                pa[i] = *(const float4*)(A + (long)(kBase + ak + i * 8) * lda + rowBase + am);
        }
    };
    auto loadB = [&](int kBase) {
#pragma unroll
        for (int i = 0; i < 2; i++)
            pb[i] = *(const float4*)(B + (long)(kBase + bk + i * 16) * ldb + colBase + bc);
    };
    auto storeA = [&]() {
        if constexpr (!TRANSA) {
#pragma unroll
            for (int i = 0; i < 4; i++)
                *(float4*)(&As[(ar + i * 32) * (BK + 4) + ac]) = pa[i];
        } else {
#pragma unroll
            for (int i = 0; i < 4; i++)
                *(float4*)(&As[(ak + i * 8) * (BM + 4) + am]) = pa[i];
        }
    };
    auto storeB = [&]() {
#pragma unroll
        for (int i = 0; i < 2; i++)
            *(float4*)(&Bs[(bk + i * 16) * (BN + 4) + bc]) = pb[i];
    };

    using ALayout = typename std::conditional<TRANSA, wmma::col_major, wmma::row_major>::type;
    using AFrag = wmma::fragment<wmma::matrix_a, 16, 16, 8, wmma::precision::tf32, ALayout>;
    using BFrag = wmma::fragment<wmma::matrix_b, 16, 16, 8, wmma::precision::tf32, wmma::row_major>;

    wmma::fragment<wmma::accumulator, 16, 16, 8, float> acc[2][2];
#pragma unroll
    for (int i = 0; i < 2; i++)
#pragma unroll
        for (int j = 0; j < 2; j++) wmma::fill_fragment(acc[i][j], 0.0f);

    loadA(0);
    loadB(0);
    storeA();
    storeB();
    __syncthreads();

    for (int kt = 0; kt < KT; kt++) {
        if (kt + 1 < KT) { loadA((kt + 1) * BK); loadB((kt + 1) * BK); }

#pragma unroll
        for (int kk = 0; kk < 4; kk++) {
            AFrag afh[2], afl[2];
            BFrag bfh[2], bfl[2];
#pragma unroll
            for (int i = 0; i < 2; i++) {
                if constexpr (!TRANSA) {
                    wmma::load_matrix_sync(afh[i], &As[(wr * 32 + i * 16) * (BK + 4) + kk * 8], BK + 4);
                } else {
                    wmma::load_matrix_sync(afh[i], &As[(kk * 8) * (BM + 4) + wr * 32 + i * 16], BM + 4);
                }
#pragma unroll
                for (int e = 0; e < afh[i].num_elements; e++) {
                    float f = afh[i].x[e];
                    float hi = wmma::__float_to_tf32(f);
                    afh[i].x[e] = hi;
                    afl[i].x[e] = wmma::__float_to_tf32(f - hi);
                }
            }
#pragma unroll
            for (int j = 0; j < 2; j++) {
                wmma::load_matrix_sync(bfh[j], &Bs[(kk * 8) * (BN + 4) + wc * 32 + j * 16], BN + 4);
#pragma unroll
                for (int e = 0; e < bfh[j].num_elements; e++) {
                    float f = bfh[j].x[e];
                    float hi = wmma::__float_to_tf32(f);
                    bfh[j].x[e] = hi;
                    bfl[j].x[e] = wmma::__float_to_tf32(f - hi);
                }
            }
            // 3xTF32: acc += Ahi*Blo + Alo*Bhi + Ahi*Bhi (small terms first)
#pragma unroll
            for (int i = 0; i < 2; i++)
#pragma unroll
                for (int j = 0; j < 2; j++) {
                    wmma::mma_sync(acc[i][j], afh[i], bfl[j], acc[i][j]);
                    wmma::mma_sync(acc[i][j], afl[i], bfh[j], acc[i][j]);
                    wmma::mma_sync(acc[i][j], afh[i], bfh[j], acc[i][j]);
                }
        }
        __syncthreads();
        if (kt + 1 < KT) {
            storeA();
            storeB();
            __syncthreads();
        }
    }

    // ------------- epilogue -------------
    if constexpr (EPI == EPI_NONE || EPI == EPI_RELU) {
#pragma unroll
        for (int i = 0; i < 2; i++)
#pragma unroll
            for (int j = 0; j < 2; j++) {
                if constexpr (EPI == EPI_RELU) {
#pragma unroll
                    for (int e = 0; e < acc[i][j].num_elements; e++)
                        acc[i][j].x[e] = fmaxf(acc[i][j].x[e], 0.0f);
                }
                wmma::store_matrix_sync(
                    C + (long)(rowBase + wr * 32 + i * 16) * ldc + colBase + wc * 32 + j * 16,
                    acc[i][j], ldc, wmma::mem_row_major);
            }
    } else {
        const float* Xa = Aux + (long)bz * sC;
        float* patch = &EpiS[warpId * 16 * 20];
        const int rr = lane >> 1;
        const int cc = (lane & 1) * 8;
#pragma unroll
        for (int i = 0; i < 2; i++)
#pragma unroll
            for (int j = 0; j < 2; j++) {
                wmma::store_matrix_sync(patch, acc[i][j], 20, wmma::mem_row_major);
                __syncwarp();
                long gr = rowBase + wr * 32 + i * 16 + rr;
                long gc = colBase + wc * 32 + j * 16 + cc;
                float4 x0 = *(const float4*)(Xa + gr * ldc + gc);
                float4 x1 = *(const float4*)(Xa + gr * ldc + gc + 4);
                float o[8];
#pragma unroll
                for (int q = 0; q < 8; q++) o[q] = fmaxf(patch[rr * 20 + cc + q], 0.0f);
                o[0] *= x0.x; o[1] *= x0.y; o[2] *= x0.z; o[3] *= x0.w;
                o[4] *= x1.x; o[5] *= x1.y; o[6] *= x1.z; o[7] *= x1.w;
                *(float4*)(C + gr * ldc + gc) = make_float4(o[0], o[1], o[2], o[3]);
                *(float4*)(C + gr * ldc + gc + 4) = make_float4(o[4], o[5], o[6], o[7]);
                __syncwarp();
            }
    }
}

// ---------------- launch -----------------------------------------------
extern "C" void kernel_launch(void* const* d_in, const int* in_sizes, int n_in,
                              void* d_out, int out_size) {
    const int* idx = (const int*)d_in[0];
    const float* emb = (const float*)d_in[1];
    const float* Dx = (const float*)d_in[2];
    const float* Dy = (const float*)d_in[3];
    const float* E = (const float*)d_in[4];
    const float* readout = (const float*)d_in[5];
    float* out = (float*)d_out;

    float *v, *x, *kv, *a, *y, *t;
    cudaGetSymbolAddress((void**)&v, g_v);
    cudaGetSymbolAddress((void**)&x, g_x);
    cudaGetSymbolAddress((void**)&kv, g_kv);
    cudaGetSymbolAddress((void**)&a, g_a);
    cudaGetSymbolAddress((void**)&y, g_y);
    cudaGetSymbolAddress((void**)&t, g_t);

    // v = emb[input]
    gather_kernel<<<BSROWS, 256>>>(idx, emb, v);

    for (int l = 0; l < NLAYERS; l++) {
        // x = relu(v @ Dx)     [4096,1024]@[1024,4096] (batch flattened)
        gemm_tf32<false, EPI_RELU><<<dim3(Nn / BN, BSROWS / BM, 1), 256>>>(
            v, Dx, x, nullptr, BSROWS, Nn, Dd, 0, 0, 0);

        // kv = x^T @ v  per batch   M=N(4096), Ncol=D(1024), K=S(2048)
        gemm_tf32<true, EPI_NONE><<<dim3(Dd / BN, Nn / BM, Bb), 256>>>(
            x, v, kv, nullptr, Nn, Dd, Ss,
            (long)Ss * Nn, (long)Ss * Dd, (long)Nn * Dd);

        // a = x @ kv  per batch     M=S(2048), Ncol=D(1024), K=N(4096)
        gemm_tf32<false, EPI_NONE><<<dim3(Dd / BN, Ss / BM, Bb), 256>>>(
            x, kv, a, nullptr, Ss, Dd, Nn,
            (long)Ss * Nn, (long)Nn * Dd, (long)Ss * Dd);

        // y = relu(a @ Dy) * x      [4096,1024]@[1024,4096]
        gemm_tf32<false, EPI_RELU_MUL><<<dim3(Nn / BN, BSROWS / BM, 1), 256>>>(
            a, Dy, y, x, BSROWS, Nn, Dd, 0, 0, 0);

        // t = y @ E                 [4096,4096]@[4096,1024]
        gemm_tf32<false, EPI_NONE><<<dim3(Dd / BN, BSROWS / BM, 1), 256>>>(
            y, E, t, nullptr, BSROWS, Dd, Nn, 0, 0, 0);

        // v = LN(v + LN(t))
        ln_res_ln_kernel<<<BSROWS, 256>>>(v, t);
    }

    // out = v @ readout           [4096,1024]@[1024,32000]
    gemm_tf32<false, EPI_NONE><<<dim3(Vv / BN, BSROWS / BM, 1), 256>>>(
        v, readout, out, nullptr, BSROWS, Vv, Dd, 0, 0, 0);
}